// round 11
// baseline (speedup 1.0000x reference)
#include <cuda_runtime.h>
#include <math.h>

#define NPTS     72
#define NSTRIPSF 71.0f
#define NLANE    4
#define NP       192
#define BATCH    512
#define DD       78
#define NBLK     1536
#define IMGW     800.0f
#define IMGH     320.0f
#define XPITCH   74
#define SPITCH   7
#define NT       576
#define NGRID    456

__device__ float    g_partials[NBLK];
__device__ unsigned g_count = 0;
__device__ unsigned g_next  = 0;

__device__ __forceinline__ unsigned umn(unsigned a, unsigned b){ return a < b ? a : b; }
__device__ __forceinline__ unsigned umx(unsigned a, unsigned b){ return a > b ? a : b; }
__device__ __forceinline__ unsigned fkey(float f){
    int b = __float_as_int(f);
    return (b >= 0) ? ((unsigned)b ^ 0x80000000u) : ~((unsigned)b);
}
__device__ __forceinline__ float smooth_l1(float x){
    float a = fabsf(x);
    return (a < 1.0f) ? 0.5f * x * x : a - 0.5f;
}
// barrier over threads 0..191 (phase-B group)
__device__ __forceinline__ void barL(){
    asm volatile("bar.sync 1, 192;" ::: "memory");
}
// barrier over threads 192..575 (stager/S group)
__device__ __forceinline__ void barR(){
    asm volatile("bar.sync 2, 384;" ::: "memory");
}

struct __align__(16) SMLayout {
    float    xs[NP * XPITCH];       // staged during B(n); read by S(n+1) — B never touches
    float    tx[NLANE * NPTS];      // same
    float    scal[2][NP * SPITCH];  // double buffer (B reads [par], stagers write [par^1])
    float    laneA[2][NLANE * 8];   // double buffer
    int      startL[2][NLANE];
    int      endL[2][NLANE];
    unsigned key[NLANE * NP];       // iter top: S half-0 plane; then B's cost keys
    float    iouc[NLANE * NP];      // iter top: S half-1 plane; then B's raw iou
    unsigned k4[NLANE][4];
    int      dks[NLANE];
    unsigned thr[NLANE];
    float    red[32];
    int      lastFlag;
    int      nextS;
};

__device__ __forceinline__ void stage_pred(SMLayout& s, const float2* __restrict__ pred2,
                                           int par, int rel, int nthr){
#pragma unroll 4
    for (int idx = rel; idx < 7488; idx += nthr){
        int r = idx / 39, c2 = idx - r * 39;
        float2 v = pred2[idx];
        if (c2 < 3){
            s.scal[par][r * SPITCH + 2 * c2]     = v.x;
            s.scal[par][r * SPITCH + 2 * c2 + 1] = v.y;
        } else {
            int c = 2 * c2 - 6;
            s.xs[r * XPITCH + c]     = v.x * (IMGW - 1.0f);
            s.xs[r * XPITCH + c + 1] = v.y * (IMGW - 1.0f);
        }
    }
}

__device__ __forceinline__ void stage_tgt(SMLayout& s, const float* __restrict__ tgt,
                                          int par, int relwid, int lane){
    if (relwid < NLANE){
        const float* t = tgt + relwid * DD;
        unsigned m[3];
#pragma unroll
        for (int c = 0; c < 3; c++){
            int j = c * 32 + lane;
            float x = (j < NPTS) ? t[6 + j] : -1.0f;
            if (j < NPTS) s.tx[relwid * NPTS + j] = x;
            m[c] = __ballot_sync(0xffffffffu, (x >= 0.0f) && (x < IMGW));
        }
        if (lane == 0){
            int nv = __popc(m[0]) + __popc(m[1]) + __popc(m[2]);
            int st = m[0] ? (__ffs(m[0]) - 1) : (m[1] ? (31 + __ffs(m[1])) : (m[2] ? (63 + __ffs(m[2])) : 0));
            int en = m[2] ? (96 - __clz(m[2])) : (m[1] ? (64 - __clz(m[1])) : (m[0] ? (32 - __clz(m[0])) : 0));
            s.startL[par][relwid] = st; s.endL[par][relwid] = en;
            float* la = s.laneA[par] + relwid * 8;
            la[0] = (t[1] == 1.0f) ? 1.0f : 0.0f;
            la[1] = (float)nv;
            la[2] = t[2]; la[3] = t[3]; la[4] = t[4]; la[5] = t[5];
            la[6] = 30.0f * (float)nv;
        }
    }
}

// S half-sum for prior p, half h (0: [st,mid), 1: [mid,en))
__device__ __forceinline__ void computeS(SMLayout& s, int par, int p, int h, float* aS){
    const float* myxs = s.xs + p * XPITCH;
#pragma unroll
    for (int l = 0; l < NLANE; l++){
        const int st0 = s.startL[par][l], en0 = s.endL[par][l];
        const int mid = (st0 + en0) >> 1;
        const int lo  = h ? mid : st0;
        const int hi  = h ? en0 : mid;
        const float* txl = s.tx + l * NPTS;
        float a0 = 0.0f, a1 = 0.0f;
        int j = lo;
        if ((j & 1) && j < hi){ a0 += fabsf(myxs[j] - txl[j]); j++; }
#pragma unroll 2
        for (; j + 1 < hi; j += 2){
            float2 a = *(const float2*)(myxs + j);
            float2 t = *(const float2*)(txl + j);
            a0 += fabsf(a.x - t.x);
            a1 += fabsf(a.y - t.y);
        }
        if (j < hi) a0 += fabsf(myxs[j] - txl[j]);
        aS[l] = a0 + a1;
    }
}

__global__ void __launch_bounds__(NT, 3)
clr_main(const float* __restrict__ predA, const float* __restrict__ tgtA,
         const float* __restrict__ seg, float* __restrict__ out)
{
    extern __shared__ char smraw[];
    SMLayout& s = *reinterpret_cast<SMLayout*>(smraw);

    const int tid  = threadIdx.x;
    const int wid  = tid >> 5;
    const int lane = tid & 31;
    const bool isB = (tid < NP);          // warps 0-5: phase-B group
    const int rel  = tid - NP;            // stager-relative id (valid if !isB)
    const int sp   = isB ? 0 : (rel & (NP - 1));   // stager's prior
    const int sh   = isB ? 0 : (rel >> 7) >> 1;    // 192..383 -> 0, 384..575 -> 1
    // (rel>>7)>>1 == rel/256? No — use explicit: half = rel >= NP
    const int half = isB ? 0 : (rel >= NP ? 1 : 0);
    (void)sp; (void)sh;
    const int p    = isB ? tid : (half ? rel - NP : rel);

    // ---- prologue: fetch first sample, everyone stages, A-group computes S ----
    if (tid == 0) s.nextS = (int)atomicAdd(&g_next, 1u);
    __syncthreads();
    int cur = s.nextS;
    int par = 0;
    {
        const float2* pred2 = (const float2*)(predA + (size_t)cur * (NP * DD));
        const float*  tgt   = tgtA + (size_t)(cur & (BATCH - 1)) * (NLANE * DD);
        stage_pred(s, pred2, par, tid, NT);
        stage_tgt(s, tgt, par, wid, lane);
    }
    __syncthreads();
    float aS[NLANE];
    if (!isB) computeS(s, par, p, half, aS);

    for (;;){
        // iteration top: publish S(cur); prefetch next index
        if (tid == 0) s.nextS = (int)atomicAdd(&g_next, 1u);
        if (!isB){
            float* plane = half ? s.iouc : (float*)s.key;
#pragma unroll
            for (int l = 0; l < NLANE; l++) plane[l * NP + p] = aS[l];
        }
        __syncthreads();
        const int nxt = s.nextS;

        if (isB){
            // ================= PHASE B(cur): threads 0..191 =================
            const float* sc1 = (const float*)s.key;
            const float* sc2 = s.iouc;
            const float* laneAp = s.laneA[par];
            float myDist[NLANE];
#pragma unroll
            for (int l = 0; l < NLANE; l++){
                float S = sc1[l * NP + tid] + sc2[l * NP + tid];
                float nv30 = laneAp[l * 8 + 6];
                float iou  = (nv30 - S) / (nv30 + S + 1e-9f);
                myDist[l]  = S / (laneAp[l * 8 + 1] + 1e-9f);
                s.iouc[l * NP + tid] = iou;      // overwrite slot just read
            }

            const float* ps = s.scal[par] + tid * SPITCH;
            const float p2 = ps[2], p3 = ps[3], p4 = ps[4];
            const float py = p2 * (IMGH - 1.0f), pxc = p3 * (IMGW - 1.0f);

            float lmD = -INFINITY, lmS = -INFINITY, lmT = -INFINITY;
            float num_t = 0.0f;
#pragma unroll
            for (int l = 0; l < NLANE; l++){
                const float* la = laneAp + l * 8;
                float v = la[0];
                num_t += v;
                float dy = py - la[2] * (IMGH - 1.0f);
                float dx = pxc - la[3];
                float sd = sqrtf(dy * dy + dx * dx);
                float th = fabsf(p4 - la[4]) * 180.0f;
                if (v > 0.0f){
                    lmD = fmaxf(lmD, myDist[l]);
                    lmS = fmaxf(lmS, sd);
                    lmT = fmaxf(lmT, th);
                }
            }
            const bool has_t = num_t > 0.0f;

#pragma unroll
            for (int o2 = 16; o2; o2 >>= 1){
                lmD = fmaxf(lmD, __shfl_xor_sync(0xffffffffu, lmD, o2));
                lmS = fmaxf(lmS, __shfl_xor_sync(0xffffffffu, lmS, o2));
                lmT = fmaxf(lmT, __shfl_xor_sync(0xffffffffu, lmT, o2));
            }
            if (lane == 0){ s.red[wid] = lmD; s.red[8 + wid] = lmS; s.red[16 + wid] = lmT; }
            barL();
            float mD = s.red[0], mS = s.red[8], mT = s.red[16];
#pragma unroll
            for (int w = 1; w < 6; w++){
                mD = fmaxf(mD, s.red[w]);
                mS = fmaxf(mS, s.red[8 + w]);
                mT = fmaxf(mT, s.red[16 + w]);
            }
            if (!has_t){ mD = 1.0f; mS = 1.0f; mT = 1.0f; }

            const float p1v = ps[1];
            float sp1  = 1.0f / (1.0f + expf(-p1v));
            float neg1 = -logf(1.0f - sp1 + 1e-12f) * 0.75f * sp1 * sp1;
            float pos1 = -logf(sp1 + 1e-12f) * 0.25f * (1.0f - sp1) * (1.0f - sp1);
            float clsc = pos1 - neg1;

            unsigned bestk = 0xFFFFFFFFu; int amin = 0;
#pragma unroll
            for (int l = 0; l < NLANE; l++){
                const float* la = laneAp + l * 8;
                float v = la[0];
                float dy = py - la[2] * (IMGH - 1.0f);
                float dx = pxc - la[3];
                float sd = sqrtf(dy * dy + dx * dx);
                float th = fabsf(p4 - la[4]) * 180.0f;
                float ds = 1.0f - myDist[l] / mD + 0.01f;
                float ss = 1.0f - sd / mS + 0.01f;
                float ts = 1.0f - th / mT + 0.01f;
                float prod = ds * ss * ts;
                float c = -(prod * prod) * 3.0f + clsc;
                c = (v > 0.0f) ? c : INFINITY;
                unsigned k = fkey(c);
                s.key[l * NP + tid] = k;
                if (k < bestk){ bestk = k; amin = l; }
            }
            barL();

            if (wid < NLANE){
                const unsigned* kcol = s.key + wid * NP;
                unsigned s0 = 0xFFFFFFFFu, s1 = 0xFFFFFFFFu, s2 = 0xFFFFFFFFu, s3 = 0xFFFFFFFFu;
#pragma unroll
                for (int c = 0; c < 6; c++){
                    unsigned x = kcol[c * 32 + lane];
                    unsigned y = umn(s3, x);
                    s3 = umx(s2, y); y = umn(s2, y);
                    s2 = umx(s1, y); y = umn(s1, y);
                    s1 = umx(s0, y); s0 = umn(s0, y);
                }
#pragma unroll
                for (int off = 16; off; off >>= 1){
                    unsigned b0 = __shfl_xor_sync(0xffffffffu, s0, off);
                    unsigned b1 = __shfl_xor_sync(0xffffffffu, s1, off);
                    unsigned b2 = __shfl_xor_sync(0xffffffffu, s2, off);
                    unsigned b3 = __shfl_xor_sync(0xffffffffu, s3, off);
                    unsigned z0 = umn(s0, b3), z1 = umn(s1, b2), z2 = umn(s2, b1), z3 = umn(s3, b0);
                    unsigned a;
                    a = umn(z0, z2); z2 = umx(z0, z2); z0 = a;
                    a = umn(z1, z3); z3 = umx(z1, z3); z1 = a;
                    a = umn(z0, z1); z1 = umx(z0, z1); z0 = a;
                    a = umn(z2, z3); z3 = umx(z2, z3); z2 = a;
                    s0 = z0; s1 = z1; s2 = z2; s3 = z3;
                }
                if (lane == 0){
                    s.k4[wid][0] = s0; s.k4[wid][1] = s1; s.k4[wid][2] = s2; s.k4[wid][3] = s3;
                }
            } else {
#pragma unroll
                for (int q = 0; q < 2; q++){
                    int l = (wid - 4) * 2 + q;
                    const float* icol = s.iouc + l * NP;
                    float t0 = 0.f, t1 = 0.f, t2 = 0.f, t3 = 0.f;
#pragma unroll
                    for (int c = 0; c < 6; c++){
                        float x = fmaxf(icol[c * 32 + lane], 0.0f);
                        float y = fmaxf(t3, x);
                        t3 = fminf(t2, y); y = fmaxf(t2, y);
                        t2 = fminf(t1, y); y = fmaxf(t1, y);
                        t1 = fminf(t0, y); t0 = fmaxf(t0, y);
                    }
#pragma unroll
                    for (int off = 16; off; off >>= 1){
                        float b0 = __shfl_xor_sync(0xffffffffu, t0, off);
                        float b1 = __shfl_xor_sync(0xffffffffu, t1, off);
                        float b2 = __shfl_xor_sync(0xffffffffu, t2, off);
                        float b3 = __shfl_xor_sync(0xffffffffu, t3, off);
                        float z0 = fmaxf(t0, b3), z1 = fmaxf(t1, b2), z2 = fmaxf(t2, b1), z3 = fmaxf(t3, b0);
                        float a;
                        a = fmaxf(z0, z2); z2 = fminf(z0, z2); z0 = a;
                        a = fmaxf(z1, z3); z3 = fminf(z1, z3); z1 = a;
                        a = fmaxf(z0, z1); z1 = fminf(z0, z1); z0 = a;
                        a = fmaxf(z2, z3); z3 = fminf(z2, z3); z2 = a;
                        t0 = z0; t1 = z1; t2 = z2; t3 = z3;
                    }
                    if (lane == 0){
                        float sum = ((t0 + t1) + t2) + t3;
                        int dk = (int)sum;
                        if (dk < 1) dk = 1; if (dk > 4) dk = 4;
                        s.dks[l] = dk;
                    }
                }
            }
            barL();
            if (tid < NLANE) s.thr[tid] = s.k4[tid][s.dks[tid] - 1];
            barL();

            int mmask = 0;
#pragma unroll
            for (int l = 0; l < NLANE; l++){
                float v = laneAp[l * 8];
                unsigned k = s.key[l * NP + tid];
                if (v > 0.0f && k <= s.thr[l]) mmask |= (1 << l);
            }
            if (__popc(mmask) > 1){ mmask &= ~1; mmask |= (1 << amin); }
            float mfsum = (float)__popc(mmask);
            int clsT = (mmask != 0) ? 1 : 0;

            const float p0v = ps[0];
            float mxl = fmaxf(p0v, p1v);
            float e0 = expf(p0v - mxl), e1 = expf(p1v - mxl);
            float pt = ((clsT ? e1 : e0) / (e0 + e1)) + 1e-8f;
            float focal = -0.25f * (1.0f - pt) * (1.0f - pt) * logf(pt);

            const float p5v = ps[5];
            float yv = p2 * NSTRIPSF, tv = p4 * 180.0f, lv = p5v * NSTRIPSF;
            float pstart = fminf(fmaxf(rintf(p2 * NSTRIPSF), 0.0f), NSTRIPSF);
            float regp = 0.0f, ioup = 0.0f;
#pragma unroll
            for (int l = 0; l < NLANE; l++){
                if (mmask & (1 << l)){
                    const float* la = laneAp + l * 8;
                    float d1 = yv - la[2] * NSTRIPSF;
                    float d2 = pxc - la[3];
                    float d3 = tv - la[4] * 180.0f;
                    float tstart = rintf(la[2] * NSTRIPSF);
                    float tlp = la[5] - (pstart - tstart);
                    float d4 = lv - tlp;
                    regp += smooth_l1(d1) + smooth_l1(d2) + smooth_l1(d3) + smooth_l1(d4);
                    ioup += 1.0f - s.iouc[l * NP + tid];
                }
            }

            float v0 = mfsum, v1 = focal, v2 = regp, v3 = ioup;
#pragma unroll
            for (int o2 = 16; o2; o2 >>= 1){
                v0 += __shfl_xor_sync(0xffffffffu, v0, o2);
                v1 += __shfl_xor_sync(0xffffffffu, v1, o2);
                v2 += __shfl_xor_sync(0xffffffffu, v2, o2);
                v3 += __shfl_xor_sync(0xffffffffu, v3, o2);
            }
            barL();
            if (lane == 0){ s.red[wid] = v0; s.red[8 + wid] = v1; s.red[16 + wid] = v2; s.red[24 + wid] = v3; }
            barL();
            if (tid == 0){
                float nmatch = 0.f, focal_s = 0.f, reg_s = 0.f, iou_s = 0.f;
#pragma unroll
                for (int w = 0; w < 6; w++){
                    nmatch  += s.red[w];
                    focal_s += s.red[8 + w];
                    reg_s   += s.red[16 + w];
                    iou_s   += s.red[24 + w];
                }
                float cls_term = focal_s / (has_t ? num_t : 1.0f);
                float reg_term = has_t ? reg_s / fmaxf(nmatch * 4.0f, 1.0f) : 0.0f;
                float iou_term = has_t ? iou_s / fmaxf(nmatch, 1.0f) : 0.0f;
                g_partials[cur] = 2.0f * cls_term + 0.2f * reg_term + 2.0f * iou_term;

                __threadfence();
                unsigned prev = atomicAdd(&g_count, 1u);
                s.lastFlag = (prev == NBLK - 1) ? 1 : 0;
            }
            barL();

            if (s.lastFlag){
                __threadfence();
                float acc = 0.0f;
#pragma unroll
                for (int k = 0; k < 8; k++)
                    acc += g_partials[tid + k * 192];
#pragma unroll
                for (int o2 = 16; o2; o2 >>= 1)
                    acc += __shfl_xor_sync(0xffffffffu, acc, o2);
                barL();
                if (lane == 0) s.red[wid] = acc;
                barL();
                if (tid == 0){
                    float tot = 0.0f;
#pragma unroll
                    for (int w = 0; w < 6; w++) tot += s.red[w];
                    out[0] = tot / (float)NBLK + seg[0];
                    __threadfence();
                    atomicExch(&g_count, 0u);
                    atomicExch(&g_next, 0u);    // safe: all fetches precede the final increment
                }
            }
        } else if (nxt < NBLK){
            // ========== stager group: stage(nxt) then compute S(nxt) ==========
            const float2* pred2n = (const float2*)(predA + (size_t)nxt * (NP * DD));
            const float*  tgtn   = tgtA + (size_t)(nxt & (BATCH - 1)) * (NLANE * DD);
            stage_pred(s, pred2n, par ^ 1, rel, NT - NP);
            stage_tgt(s, tgtn, par ^ 1, rel >> 5, lane);
            barR();                               // staging complete within group
            computeS(s, par ^ 1, p, half, aS);    // S(n+1) into registers
        }
        __syncthreads();
        if (nxt >= NBLK) break;
        cur = nxt; par ^= 1;
    }
}

extern "C" void kernel_launch(void* const* d_in, const int* in_sizes, int n_in,
                              void* d_out, int out_size)
{
    const float* pred = (const float*)d_in[0];
    const float* tgt  = (const float*)d_in[1];
    const float* seg  = (const float*)d_in[2];
    float* out = (float*)d_out;

    static int attr_set = 0;
    const int smem = (int)sizeof(SMLayout);
    if (!attr_set){
        cudaFuncSetAttribute(clr_main, cudaFuncAttributeMaxDynamicSharedMemorySize, smem);
        attr_set = 1;
    }
    clr_main<<<NGRID, NT, smem>>>(pred, tgt, seg, out);
}

// round 12
// speedup vs baseline: 1.1501x; 1.1501x over previous
#include <cuda_runtime.h>
#include <math.h>

#define NPTS     72
#define NSTRIPSF 71.0f
#define NLANE    4
#define NP       192
#define BATCH    512
#define DD       78
#define NBLK     1536
#define IMGW     800.0f
#define IMGH     320.0f
#define XPITCH   74
#define SPITCH   7
#define NT       576

__device__ float    g_partials[NBLK];
__device__ unsigned g_count = 0;

__device__ __forceinline__ unsigned umn(unsigned a, unsigned b){ return a < b ? a : b; }
__device__ __forceinline__ unsigned umx(unsigned a, unsigned b){ return a > b ? a : b; }
__device__ __forceinline__ unsigned fkey(float f){
    int b = __float_as_int(f);
    return (b >= 0) ? ((unsigned)b ^ 0x80000000u) : ~((unsigned)b);
}
__device__ __forceinline__ float smooth_l1(float x){
    float a = fabsf(x);
    return (a < 1.0f) ? 0.5f * x * x : a - 0.5f;
}
// partial barrier over threads 0..191 (warps 0-5)
__device__ __forceinline__ void barL(){
    asm volatile("bar.sync 1, 192;" ::: "memory");
}

struct __align__(16) SMLayout {
    float    xs[NP * XPITCH];     // pred xs premultiplied by 799 (pitch 74: LDS.64 conflict-free)
    float    scal[NP * SPITCH];   // p0..p5
    float    tx[NLANE * NPTS];    // raw target xs per lane
    unsigned key[NLANE * NP];     // PHASE A: scratch plane 1; PHASE B: cost keys
    float    iouc[NLANE * NP];    // PHASE A: scratch plane 2; PHASE B: raw iou
    float    laneA[NLANE * 8];    // [0]=valid [1]=1/(nv+1e-9) [2..5]=t2..5 [6]=30*nv
    int      startL[NLANE], endL[NLANE];
    unsigned k4[NLANE][4];
    int      dks[NLANE];
    unsigned thr[NLANE];
    float    red[32];
    int      lastFlag;
};

__global__ void __launch_bounds__(NT, 3)
clr_main(const float* __restrict__ predA, const float* __restrict__ tgtA,
         const float* __restrict__ seg, float* __restrict__ out)
{
    extern __shared__ char smraw[];
    SMLayout& s = *reinterpret_cast<SMLayout*>(smraw);

    const int tid  = threadIdx.x;
    const int wid  = tid >> 5;
    const int lane = tid & 31;
    const int g    = tid / NP;           // third index 0,1,2
    const int p    = tid - g * NP;       // prior index
    const int blk  = blockIdx.x;
    const int b    = blk & (BATCH - 1);

    const float2* pred2 = (const float2*)(predA + (size_t)blk * (NP * DD));
    const float*  tgt   = tgtA + (size_t)b * (NLANE * DD);

    // ---- stage predictions (coalesced float2; 13*576 = 7488 exact) ----
#pragma unroll 4
    for (int k = 0; k < 13; k++){
        int idx = tid + k * NT;
        int r = idx / 39, c2 = idx - r * 39;
        float2 v = pred2[idx];
        if (c2 < 3){
            s.scal[r * SPITCH + 2 * c2]     = v.x;
            s.scal[r * SPITCH + 2 * c2 + 1] = v.y;
        } else {
            int c = 2 * c2 - 6;
            s.xs[r * XPITCH + c]     = v.x * (IMGW - 1.0f);
            s.xs[r * XPITCH + c + 1] = v.y * (IMGW - 1.0f);
        }
    }

    // ---- stage targets, find contiguous valid run per lane (warps 0..3) ----
    if (wid < NLANE){
        const float* t = tgt + wid * DD;
        unsigned m[3];
#pragma unroll
        for (int c = 0; c < 3; c++){
            int j = c * 32 + lane;
            float x = (j < NPTS) ? t[6 + j] : -1.0f;
            if (j < NPTS) s.tx[wid * NPTS + j] = x;
            m[c] = __ballot_sync(0xffffffffu, (x >= 0.0f) && (x < IMGW));
        }
        if (lane == 0){
            int nv = __popc(m[0]) + __popc(m[1]) + __popc(m[2]);
            int st = m[0] ? (__ffs(m[0]) - 1) : (m[1] ? (31 + __ffs(m[1])) : (m[2] ? (63 + __ffs(m[2])) : 0));
            int en = m[2] ? (96 - __clz(m[2])) : (m[1] ? (64 - __clz(m[1])) : (m[0] ? (32 - __clz(m[0])) : 0));
            s.startL[wid] = st; s.endL[wid] = en;
            float* la = s.laneA + wid * 8;
            la[0] = (t[1] == 1.0f) ? 1.0f : 0.0f;
            la[1] = 1.0f / ((float)nv + 1e-9f);      // hoisted reciprocal (full precision, once)
            la[2] = t[2]; la[3] = t[3]; la[4] = t[4]; la[5] = t[5];
            la[6] = 30.0f * (float)nv;
        }
    }
    __syncthreads();

    // ---- S third-loop: thread (p, g) sums its j-third via float2 ----
    const float* myxs = s.xs + p * XPITCH;
    float aS[NLANE];
#pragma unroll
    for (int l = 0; l < NLANE; l++){
        const int st0 = s.startL[l], en0 = s.endL[l];
        const int n   = en0 - st0;
        const int b1  = st0 + n / 3;
        const int b2  = st0 + (2 * n) / 3;
        const int lo  = (g == 0) ? st0 : (g == 1) ? b1 : b2;
        const int hi  = (g == 0) ? b1  : (g == 1) ? b2 : en0;
        const float* txl = s.tx + l * NPTS;
        float a0 = 0.0f, a1 = 0.0f;
        int j = lo;
        if ((j & 1) && j < hi){ a0 += fabsf(myxs[j] - txl[j]); j++; }
#pragma unroll 2
        for (; j + 1 < hi; j += 2){
            float2 a = *(const float2*)(myxs + j);
            float2 t = *(const float2*)(txl + j);
            a0 += fabsf(a.x - t.x);
            a1 += fabsf(a.y - t.y);
        }
        if (j < hi) a0 += fabsf(myxs[j] - txl[j]);
        aS[l] = a0 + a1;
    }
    {
        float* sc1 = (float*)s.key;
        float* sc2 = s.iouc;
        if (g == 1){
#pragma unroll
            for (int l = 0; l < NLANE; l++) sc1[l * NP + p] = aS[l];
        } else if (g == 2){
#pragma unroll
            for (int l = 0; l < NLANE; l++) sc2[l * NP + p] = aS[l];
        }
    }
    __syncthreads();
    if (tid >= NP) return;          // warps 6-17 done; warps 0-5 use named barriers only

    // ================= PHASE B: threads 0..191 =================
    const float* sc1 = (const float*)s.key;
    const float* sc2 = s.iouc;
    float myDist[NLANE];
#pragma unroll
    for (int l = 0; l < NLANE; l++){
        float S = (aS[l] + sc1[l * NP + tid]) + sc2[l * NP + tid];
        float nv30 = s.laneA[l * 8 + 6];
        float iou  = __fdividef(nv30 - S, nv30 + S + 1e-9f);
        myDist[l]  = S * s.laneA[l * 8 + 1];
        s.iouc[l * NP + tid] = iou;          // raw iou (same slot this thread read)
    }

    const float* ps = s.scal + tid * SPITCH;
    const float p2 = ps[2], p3 = ps[3], p4 = ps[4];
    const float py = p2 * (IMGH - 1.0f), pxc = p3 * (IMGW - 1.0f);

    // ---- per-lane sd/th (kept in regs) + local maxima ----
    float mySd[NLANE], myTh[NLANE], vL[NLANE];
    float lmD = -INFINITY, lmS = -INFINITY, lmT = -INFINITY;
    float num_t = 0.0f;
#pragma unroll
    for (int l = 0; l < NLANE; l++){
        const float* la = s.laneA + l * 8;
        float v = la[0]; vL[l] = v;
        num_t += v;
        float dy = py - la[2] * (IMGH - 1.0f);
        float dx = pxc - la[3];
        float sd = sqrtf(dy * dy + dx * dx);
        float th = fabsf(p4 - la[4]) * 180.0f;
        mySd[l] = sd; myTh[l] = th;
        if (v > 0.0f){
            lmD = fmaxf(lmD, myDist[l]);
            lmS = fmaxf(lmS, sd);
            lmT = fmaxf(lmT, th);
        }
    }
    const bool has_t = num_t > 0.0f;

    // ---- fused 3-way block max over 192 threads ----
#pragma unroll
    for (int o2 = 16; o2; o2 >>= 1){
        lmD = fmaxf(lmD, __shfl_xor_sync(0xffffffffu, lmD, o2));
        lmS = fmaxf(lmS, __shfl_xor_sync(0xffffffffu, lmS, o2));
        lmT = fmaxf(lmT, __shfl_xor_sync(0xffffffffu, lmT, o2));
    }
    if (lane == 0){ s.red[wid] = lmD; s.red[8 + wid] = lmS; s.red[16 + wid] = lmT; }
    barL();
    float mD = s.red[0], mS = s.red[8], mT = s.red[16];
#pragma unroll
    for (int w = 1; w < 6; w++){
        mD = fmaxf(mD, s.red[w]);
        mS = fmaxf(mS, s.red[8 + w]);
        mT = fmaxf(mT, s.red[16 + w]);
    }
    if (!has_t){ mD = 1.0f; mS = 1.0f; mT = 1.0f; }
    const float rmD = __fdividef(1.0f, mD);
    const float rmS = __fdividef(1.0f, mS);
    const float rmT = __fdividef(1.0f, mT);

    // ---- classification cost (fast transcendentals) ----
    const float p1v = ps[1];
    float e1n  = __expf(-p1v);
    float sp1  = __fdividef(1.0f, 1.0f + e1n);
    float neg1 = -__logf(1.0f - sp1 + 1e-12f) * 0.75f * sp1 * sp1;
    float pos1 = -__logf(sp1 + 1e-12f) * 0.25f * (1.0f - sp1) * (1.0f - sp1);
    float clsc = pos1 - neg1;

    // ---- cost loop: reciprocal multiplies, emit keys; track amin via key ----
    unsigned bestk = 0xFFFFFFFFu; int amin = 0;
#pragma unroll
    for (int l = 0; l < NLANE; l++){
        float ds = 1.0f - myDist[l] * rmD + 0.01f;
        float ss = 1.0f - mySd[l]  * rmS + 0.01f;
        float ts = 1.0f - myTh[l]  * rmT + 0.01f;
        float prod = ds * ss * ts;
        float c = -(prod * prod) * 3.0f + clsc;
        c = (vL[l] > 0.0f) ? c : INFINITY;
        unsigned k = fkey(c);
        s.key[l * NP + tid] = k;
        if (k < bestk){ bestk = k; amin = l; }
    }
    barL();

    // ---- selection: warps 0-3 cost-key top4; warps 4-5 iou top4 -> dyn_k ----
    if (wid < NLANE){
        const unsigned* kcol = s.key + wid * NP;
        unsigned s0 = 0xFFFFFFFFu, s1 = 0xFFFFFFFFu, s2 = 0xFFFFFFFFu, s3 = 0xFFFFFFFFu;
#pragma unroll
        for (int c = 0; c < 6; c++){
            unsigned x = kcol[c * 32 + lane];
            unsigned y = umn(s3, x);
            s3 = umx(s2, y); y = umn(s2, y);
            s2 = umx(s1, y); y = umn(s1, y);
            s1 = umx(s0, y); s0 = umn(s0, y);
        }
#pragma unroll
        for (int off = 16; off; off >>= 1){
            unsigned b0 = __shfl_xor_sync(0xffffffffu, s0, off);
            unsigned b1 = __shfl_xor_sync(0xffffffffu, s1, off);
            unsigned b2 = __shfl_xor_sync(0xffffffffu, s2, off);
            unsigned b3 = __shfl_xor_sync(0xffffffffu, s3, off);
            unsigned z0 = umn(s0, b3), z1 = umn(s1, b2), z2 = umn(s2, b1), z3 = umn(s3, b0);
            unsigned a;
            a = umn(z0, z2); z2 = umx(z0, z2); z0 = a;
            a = umn(z1, z3); z3 = umx(z1, z3); z1 = a;
            a = umn(z0, z1); z1 = umx(z0, z1); z0 = a;
            a = umn(z2, z3); z3 = umx(z2, z3); z2 = a;
            s0 = z0; s1 = z1; s2 = z2; s3 = z3;
        }
        if (lane == 0){
            s.k4[wid][0] = s0; s.k4[wid][1] = s1; s.k4[wid][2] = s2; s.k4[wid][3] = s3;
        }
    } else {
#pragma unroll
        for (int q = 0; q < 2; q++){
            int l = (wid - 4) * 2 + q;
            const float* icol = s.iouc + l * NP;
            float t0 = 0.f, t1 = 0.f, t2 = 0.f, t3 = 0.f;
#pragma unroll
            for (int c = 0; c < 6; c++){
                float x = fmaxf(icol[c * 32 + lane], 0.0f);   // clamp raw iou
                float y = fmaxf(t3, x);
                t3 = fminf(t2, y); y = fmaxf(t2, y);
                t2 = fminf(t1, y); y = fmaxf(t1, y);
                t1 = fminf(t0, y); t0 = fmaxf(t0, y);
            }
#pragma unroll
            for (int off = 16; off; off >>= 1){
                float b0 = __shfl_xor_sync(0xffffffffu, t0, off);
                float b1 = __shfl_xor_sync(0xffffffffu, t1, off);
                float b2 = __shfl_xor_sync(0xffffffffu, t2, off);
                float b3 = __shfl_xor_sync(0xffffffffu, t3, off);
                float z0 = fmaxf(t0, b3), z1 = fmaxf(t1, b2), z2 = fmaxf(t2, b1), z3 = fmaxf(t3, b0);
                float a;
                a = fmaxf(z0, z2); z2 = fminf(z0, z2); z0 = a;
                a = fmaxf(z1, z3); z3 = fminf(z1, z3); z1 = a;
                a = fmaxf(z0, z1); z1 = fminf(z0, z1); z0 = a;
                a = fmaxf(z2, z3); z3 = fminf(z2, z3); z2 = a;
                t0 = z0; t1 = z1; t2 = z2; t3 = z3;
            }
            if (lane == 0){
                float sum = ((t0 + t1) + t2) + t3;
                int dk = (int)sum;
                if (dk < 1) dk = 1; if (dk > 4) dk = 4;
                s.dks[l] = dk;
            }
        }
    }
    barL();
    if (tid < NLANE) s.thr[tid] = s.k4[tid][s.dks[tid] - 1];
    barL();

    // ---- matching (bitmask) ----
    int mmask = 0;
#pragma unroll
    for (int l = 0; l < NLANE; l++){
        unsigned k = s.key[l * NP + tid];
        if (vL[l] > 0.0f && k <= s.thr[l]) mmask |= (1 << l);
    }
    if (__popc(mmask) > 1){ mmask &= ~1; mmask |= (1 << amin); }
    float mfsum = (float)__popc(mmask);
    int clsT = (mmask != 0) ? 1 : 0;

    // ---- focal (fast transcendentals) ----
    const float p0v = ps[0];
    float mxl = fmaxf(p0v, p1v);
    float e0 = __expf(p0v - mxl), e1 = __expf(p1v - mxl);
    float pt = __fdividef(clsT ? e1 : e0, e0 + e1) + 1e-8f;
    float focal = -0.25f * (1.0f - pt) * (1.0f - pt) * __logf(pt);

    // ---- reg + iou epilogue ----
    const float p5v = ps[5];
    float yv = p2 * NSTRIPSF, tv = p4 * 180.0f, lv = p5v * NSTRIPSF;
    float pstart = fminf(fmaxf(rintf(p2 * NSTRIPSF), 0.0f), NSTRIPSF);
    float regp = 0.0f, ioup = 0.0f;
#pragma unroll
    for (int l = 0; l < NLANE; l++){
        if (mmask & (1 << l)){
            const float* la = s.laneA + l * 8;
            float d1 = yv - la[2] * NSTRIPSF;
            float d2 = pxc - la[3];
            float d3 = tv - la[4] * 180.0f;
            float tstart = rintf(la[2] * NSTRIPSF);
            float tlp = la[5] - (pstart - tstart);
            float d4 = lv - tlp;
            regp += smooth_l1(d1) + smooth_l1(d2) + smooth_l1(d3) + smooth_l1(d4);
            ioup += 1.0f - s.iouc[l * NP + tid];
        }
    }

    // ---- fused 4-way block sum over 192 threads ----
    float v0 = mfsum, v1 = focal, v2 = regp, v3 = ioup;
#pragma unroll
    for (int o2 = 16; o2; o2 >>= 1){
        v0 += __shfl_xor_sync(0xffffffffu, v0, o2);
        v1 += __shfl_xor_sync(0xffffffffu, v1, o2);
        v2 += __shfl_xor_sync(0xffffffffu, v2, o2);
        v3 += __shfl_xor_sync(0xffffffffu, v3, o2);
    }
    barL();
    if (lane == 0){ s.red[wid] = v0; s.red[8 + wid] = v1; s.red[16 + wid] = v2; s.red[24 + wid] = v3; }
    barL();
    if (tid == 0){
        float nmatch = 0.f, focal_s = 0.f, reg_s = 0.f, iou_s = 0.f;
#pragma unroll
        for (int w = 0; w < 6; w++){
            nmatch  += s.red[w];
            focal_s += s.red[8 + w];
            reg_s   += s.red[16 + w];
            iou_s   += s.red[24 + w];
        }
        float cls_term = has_t ? __fdividef(focal_s, num_t) : focal_s;
        float reg_term = has_t ? __fdividef(reg_s, fmaxf(nmatch * 4.0f, 1.0f)) : 0.0f;
        float iou_term = has_t ? __fdividef(iou_s, fmaxf(nmatch, 1.0f)) : 0.0f;
        g_partials[blk] = 2.0f * cls_term + 0.2f * reg_term + 2.0f * iou_term;

        __threadfence();
        unsigned prev = atomicAdd(&g_count, 1u);
        s.lastFlag = (prev == NBLK - 1) ? 1 : 0;
    }
    barL();

    // ---- last block: deterministic final reduction ----
    if (s.lastFlag){
        __threadfence();
        float acc = 0.0f;
#pragma unroll
        for (int k = 0; k < 8; k++)
            acc += g_partials[tid + k * 192];
#pragma unroll
        for (int o2 = 16; o2; o2 >>= 1)
            acc += __shfl_xor_sync(0xffffffffu, acc, o2);
        barL();
        if (lane == 0) s.red[wid] = acc;
        barL();
        if (tid == 0){
            float tot = 0.0f;
#pragma unroll
            for (int w = 0; w < 6; w++) tot += s.red[w];
            out[0] = tot / (float)NBLK + seg[0];
            g_count = 0;
        }
    }
}

extern "C" void kernel_launch(void* const* d_in, const int* in_sizes, int n_in,
                              void* d_out, int out_size)
{
    const float* pred = (const float*)d_in[0];
    const float* tgt  = (const float*)d_in[1];
    const float* seg  = (const float*)d_in[2];
    float* out = (float*)d_out;

    static int attr_set = 0;
    const int smem = (int)sizeof(SMLayout);
    if (!attr_set){
        cudaFuncSetAttribute(clr_main, cudaFuncAttributeMaxDynamicSharedMemorySize, smem);
        attr_set = 1;
    }
    clr_main<<<NBLK, NT, smem>>>(pred, tgt, seg, out);
}

// round 13
// speedup vs baseline: 1.2565x; 1.0925x over previous
#include <cuda_runtime.h>
#include <math.h>

#define NPTS     72
#define NSTRIPSF 71.0f
#define NLANE    4
#define NP       192
#define BATCH    512
#define DD       78
#define NBLK     1536
#define IMGW     800.0f
#define IMGH     320.0f
#define RPITCH   82          // unified row pitch: cols 0-5 scalars, 6-77 raw xs
#define NT       576
#define INV_W    (1.0f/799.0f)

__device__ float    g_partials[NBLK];
__device__ unsigned g_count = 0;

__device__ __forceinline__ unsigned umn(unsigned a, unsigned b){ return a < b ? a : b; }
__device__ __forceinline__ unsigned umx(unsigned a, unsigned b){ return a > b ? a : b; }
__device__ __forceinline__ unsigned fkey(float f){
    int b = __float_as_int(f);
    return (b >= 0) ? ((unsigned)b ^ 0x80000000u) : ~((unsigned)b);
}
__device__ __forceinline__ float smooth_l1(float x){
    float a = fabsf(x);
    return (a < 1.0f) ? 0.5f * x * x : a - 0.5f;
}
// partial barrier over threads 0..191 (warps 0-5)
__device__ __forceinline__ void barL(){
    asm volatile("bar.sync 1, 192;" ::: "memory");
}

struct __align__(16) SMLayout {
    float    row[NP * RPITCH];    // unified prediction tile (raw copy of all 78 cols)
    float    tx[NLANE * NPTS];    // target xs PRE-SCALED by 1/799
    unsigned key[NLANE * NP];     // PHASE A: scratch plane 1; PHASE B: cost keys
    float    iouc[NLANE * NP];    // PHASE A: scratch plane 2; PHASE B: raw iou
    float    laneA[NLANE * 8];    // [0]=valid [1]=1/(nv+1e-9) [2..5]=t2..5 [6]=30*nv
    int      startL[NLANE], endL[NLANE];
    unsigned k4[NLANE][4];
    int      dks[NLANE];
    unsigned thr[NLANE];
    float    red[32];
    int      lastFlag;
};

__global__ void __launch_bounds__(NT, 3)
clr_main(const float* __restrict__ predA, const float* __restrict__ tgtA,
         const float* __restrict__ seg, float* __restrict__ out)
{
    extern __shared__ char smraw[];
    SMLayout& s = *reinterpret_cast<SMLayout*>(smraw);

    const int tid  = threadIdx.x;
    const int wid  = tid >> 5;
    const int lane = tid & 31;
    const int g    = tid / NP;           // third index 0,1,2
    const int p    = tid - g * NP;       // prior index
    const int blk  = blockIdx.x;
    const int b    = blk & (BATCH - 1);

    const float2* pred2 = (const float2*)(predA + (size_t)blk * (NP * DD));
    const float*  tgt   = tgtA + (size_t)b * (NLANE * DD);

    // ---- stage predictions: raw coalesced copy (13*576 = 7488 float2 exact) ----
#pragma unroll 4
    for (int k = 0; k < 13; k++){
        int idx = tid + k * NT;
        int r = idx / 39, c2 = idx - r * 39;
        float2 v = pred2[idx];
        *(float2*)(s.row + r * RPITCH + 2 * c2) = v;   // 8B-aligned (82*4*r + 8*c2)
    }

    // ---- stage targets (pre-scaled), find contiguous valid run (warps 0..3) ----
    if (wid < NLANE){
        const float* t = tgt + wid * DD;
        unsigned m[3];
#pragma unroll
        for (int c = 0; c < 3; c++){
            int j = c * 32 + lane;
            float x = (j < NPTS) ? t[6 + j] : -1.0f;
            if (j < NPTS) s.tx[wid * NPTS + j] = x * INV_W;   // pre-scaled
            m[c] = __ballot_sync(0xffffffffu, (x >= 0.0f) && (x < IMGW));
        }
        if (lane == 0){
            int nv = __popc(m[0]) + __popc(m[1]) + __popc(m[2]);
            int st = m[0] ? (__ffs(m[0]) - 1) : (m[1] ? (31 + __ffs(m[1])) : (m[2] ? (63 + __ffs(m[2])) : 0));
            int en = m[2] ? (96 - __clz(m[2])) : (m[1] ? (64 - __clz(m[1])) : (m[0] ? (32 - __clz(m[0])) : 0));
            s.startL[wid] = st; s.endL[wid] = en;
            float* la = s.laneA + wid * 8;
            la[0] = (t[1] == 1.0f) ? 1.0f : 0.0f;
            la[1] = 1.0f / ((float)nv + 1e-9f);
            la[2] = t[2]; la[3] = t[3]; la[4] = t[4]; la[5] = t[5];
            la[6] = 30.0f * (float)nv;
        }
    }
    __syncthreads();

    // ---- S third-loop (normalized units): thread (p,g) sums its j-third ----
    const float* myxs = s.row + p * RPITCH + 6;    // raw xs in [0,1]
    float aS[NLANE];
#pragma unroll
    for (int l = 0; l < NLANE; l++){
        const int st0 = s.startL[l], en0 = s.endL[l];
        const int n   = en0 - st0;
        const int b1  = st0 + n / 3;
        const int b2  = st0 + (2 * n) / 3;
        const int lo  = (g == 0) ? st0 : (g == 1) ? b1 : b2;
        const int hi  = (g == 0) ? b1  : (g == 1) ? b2 : en0;
        const float* txl = s.tx + l * NPTS;
        float a0 = 0.0f, a1 = 0.0f;
        int j = lo;
        if ((j & 1) && j < hi){ a0 += fabsf(myxs[j] - txl[j]); j++; }
#pragma unroll 4
        for (; j + 1 < hi; j += 2){
            float2 a = *(const float2*)(myxs + j);
            float2 t = *(const float2*)(txl + j);
            a0 += fabsf(a.x - t.x);
            a1 += fabsf(a.y - t.y);
        }
        if (j < hi) a0 += fabsf(myxs[j] - txl[j]);
        aS[l] = a0 + a1;
    }
    {
        float* sc1 = (float*)s.key;
        float* sc2 = s.iouc;
        if (g == 1){
#pragma unroll
            for (int l = 0; l < NLANE; l++) sc1[l * NP + p] = aS[l];
        } else if (g == 2){
#pragma unroll
            for (int l = 0; l < NLANE; l++) sc2[l * NP + p] = aS[l];
        }
    }
    __syncthreads();
    if (tid >= NP) return;          // warps 6-17 done; warps 0-5 use named barriers only

    // ================= PHASE B: threads 0..191 =================
    const float* sc1 = (const float*)s.key;
    const float* sc2 = s.iouc;
    float myDist[NLANE];
#pragma unroll
    for (int l = 0; l < NLANE; l++){
        float Sr = (aS[l] + sc1[l * NP + tid]) + sc2[l * NP + tid];
        float S  = Sr * (IMGW - 1.0f);               // back to pixel units
        float nv30 = s.laneA[l * 8 + 6];
        float iou  = __fdividef(nv30 - S, nv30 + S + 1e-9f);
        myDist[l]  = S * s.laneA[l * 8 + 1];
        s.iouc[l * NP + tid] = iou;                  // raw iou (same slot this thread read)
    }

    const float* ps = s.row + tid * RPITCH;          // cols 0-5 = p0..p5
    const float p2 = ps[2], p3 = ps[3], p4 = ps[4];
    const float py = p2 * (IMGH - 1.0f), pxc = p3 * (IMGW - 1.0f);

    // ---- per-lane sd/th (kept in regs) + local maxima ----
    float mySd[NLANE], myTh[NLANE], vL[NLANE];
    float lmD = -INFINITY, lmS = -INFINITY, lmT = -INFINITY;
    float num_t = 0.0f;
#pragma unroll
    for (int l = 0; l < NLANE; l++){
        const float* la = s.laneA + l * 8;
        float v = la[0]; vL[l] = v;
        num_t += v;
        float dy = py - la[2] * (IMGH - 1.0f);
        float dx = pxc - la[3];
        float sd = sqrtf(dy * dy + dx * dx);
        float th = fabsf(p4 - la[4]) * 180.0f;
        mySd[l] = sd; myTh[l] = th;
        if (v > 0.0f){
            lmD = fmaxf(lmD, myDist[l]);
            lmS = fmaxf(lmS, sd);
            lmT = fmaxf(lmT, th);
        }
    }
    const bool has_t = num_t > 0.0f;

    // ---- fused 3-way block max over 192 threads ----
#pragma unroll
    for (int o2 = 16; o2; o2 >>= 1){
        lmD = fmaxf(lmD, __shfl_xor_sync(0xffffffffu, lmD, o2));
        lmS = fmaxf(lmS, __shfl_xor_sync(0xffffffffu, lmS, o2));
        lmT = fmaxf(lmT, __shfl_xor_sync(0xffffffffu, lmT, o2));
    }
    if (lane == 0){ s.red[wid] = lmD; s.red[8 + wid] = lmS; s.red[16 + wid] = lmT; }
    barL();
    float mD = s.red[0], mS = s.red[8], mT = s.red[16];
#pragma unroll
    for (int w = 1; w < 6; w++){
        mD = fmaxf(mD, s.red[w]);
        mS = fmaxf(mS, s.red[8 + w]);
        mT = fmaxf(mT, s.red[16 + w]);
    }
    if (!has_t){ mD = 1.0f; mS = 1.0f; mT = 1.0f; }
    const float rmD = __fdividef(1.0f, mD);
    const float rmS = __fdividef(1.0f, mS);
    const float rmT = __fdividef(1.0f, mT);

    // ---- classification cost (fast transcendentals) ----
    const float p1v = ps[1];
    float e1n  = __expf(-p1v);
    float sp1  = __fdividef(1.0f, 1.0f + e1n);
    float neg1 = -__logf(1.0f - sp1 + 1e-12f) * 0.75f * sp1 * sp1;
    float pos1 = -__logf(sp1 + 1e-12f) * 0.25f * (1.0f - sp1) * (1.0f - sp1);
    float clsc = pos1 - neg1;

    // ---- cost loop: emit keys (kept in regs); track amin via key ----
    unsigned mykey[NLANE];
    unsigned bestk = 0xFFFFFFFFu; int amin = 0;
#pragma unroll
    for (int l = 0; l < NLANE; l++){
        float ds = 1.0f - myDist[l] * rmD + 0.01f;
        float ss = 1.0f - mySd[l]  * rmS + 0.01f;
        float ts = 1.0f - myTh[l]  * rmT + 0.01f;
        float prod = ds * ss * ts;
        float c = -(prod * prod) * 3.0f + clsc;
        c = (vL[l] > 0.0f) ? c : INFINITY;
        unsigned k = fkey(c);
        mykey[l] = k;
        s.key[l * NP + tid] = k;
        if (k < bestk){ bestk = k; amin = l; }
    }
    barL();

    // ---- selection: warps 0-3 cost-key top4; warps 4-5 iou top4 -> dyn_k ----
    if (wid < NLANE){
        const unsigned* kcol = s.key + wid * NP;
        unsigned s0 = 0xFFFFFFFFu, s1 = 0xFFFFFFFFu, s2 = 0xFFFFFFFFu, s3 = 0xFFFFFFFFu;
#pragma unroll
        for (int c = 0; c < 6; c++){
            unsigned x = kcol[c * 32 + lane];
            unsigned y = umn(s3, x);
            s3 = umx(s2, y); y = umn(s2, y);
            s2 = umx(s1, y); y = umn(s1, y);
            s1 = umx(s0, y); s0 = umn(s0, y);
        }
#pragma unroll
        for (int off = 16; off; off >>= 1){
            unsigned b0 = __shfl_xor_sync(0xffffffffu, s0, off);
            unsigned b1 = __shfl_xor_sync(0xffffffffu, s1, off);
            unsigned b2 = __shfl_xor_sync(0xffffffffu, s2, off);
            unsigned b3 = __shfl_xor_sync(0xffffffffu, s3, off);
            unsigned z0 = umn(s0, b3), z1 = umn(s1, b2), z2 = umn(s2, b1), z3 = umn(s3, b0);
            unsigned a;
            a = umn(z0, z2); z2 = umx(z0, z2); z0 = a;
            a = umn(z1, z3); z3 = umx(z1, z3); z1 = a;
            a = umn(z0, z1); z1 = umx(z0, z1); z0 = a;
            a = umn(z2, z3); z3 = umx(z2, z3); z2 = a;
            s0 = z0; s1 = z1; s2 = z2; s3 = z3;
        }
        if (lane == 0){
            s.k4[wid][0] = s0; s.k4[wid][1] = s1; s.k4[wid][2] = s2; s.k4[wid][3] = s3;
        }
    } else {
#pragma unroll
        for (int q = 0; q < 2; q++){
            int l = (wid - 4) * 2 + q;
            const float* icol = s.iouc + l * NP;
            float t0 = 0.f, t1 = 0.f, t2 = 0.f, t3 = 0.f;
#pragma unroll
            for (int c = 0; c < 6; c++){
                float x = fmaxf(icol[c * 32 + lane], 0.0f);   // clamp raw iou
                float y = fmaxf(t3, x);
                t3 = fminf(t2, y); y = fmaxf(t2, y);
                t2 = fminf(t1, y); y = fmaxf(t1, y);
                t1 = fminf(t0, y); t0 = fmaxf(t0, y);
            }
#pragma unroll
            for (int off = 16; off; off >>= 1){
                float b0 = __shfl_xor_sync(0xffffffffu, t0, off);
                float b1 = __shfl_xor_sync(0xffffffffu, t1, off);
                float b2 = __shfl_xor_sync(0xffffffffu, t2, off);
                float b3 = __shfl_xor_sync(0xffffffffu, t3, off);
                float z0 = fmaxf(t0, b3), z1 = fmaxf(t1, b2), z2 = fmaxf(t2, b1), z3 = fmaxf(t3, b0);
                float a;
                a = fmaxf(z0, z2); z2 = fminf(z0, z2); z0 = a;
                a = fmaxf(z1, z3); z3 = fminf(z1, z3); z1 = a;
                a = fmaxf(z0, z1); z1 = fminf(z0, z1); z0 = a;
                a = fmaxf(z2, z3); z3 = fminf(z2, z3); z2 = a;
                t0 = z0; t1 = z1; t2 = z2; t3 = z3;
            }
            if (lane == 0){
                float sum = ((t0 + t1) + t2) + t3;
                int dk = (int)sum;
                if (dk < 1) dk = 1; if (dk > 4) dk = 4;
                s.dks[l] = dk;
            }
        }
    }
    barL();
    if (tid < NLANE) s.thr[tid] = s.k4[tid][s.dks[tid] - 1];
    barL();

    // ---- matching (bitmask, keys from registers) ----
    int mmask = 0;
#pragma unroll
    for (int l = 0; l < NLANE; l++){
        if (vL[l] > 0.0f && mykey[l] <= s.thr[l]) mmask |= (1 << l);
    }
    if (__popc(mmask) > 1){ mmask &= ~1; mmask |= (1 << amin); }
    float mfsum = (float)__popc(mmask);
    int clsT = (mmask != 0) ? 1 : 0;

    // ---- focal (fast transcendentals) ----
    const float p0v = ps[0];
    float mxl = fmaxf(p0v, p1v);
    float e0 = __expf(p0v - mxl), e1 = __expf(p1v - mxl);
    float pt = __fdividef(clsT ? e1 : e0, e0 + e1) + 1e-8f;
    float focal = -0.25f * (1.0f - pt) * (1.0f - pt) * __logf(pt);

    // ---- reg + iou epilogue ----
    const float p5v = ps[5];
    float yv = p2 * NSTRIPSF, tv = p4 * 180.0f, lv = p5v * NSTRIPSF;
    float pstart = fminf(fmaxf(rintf(p2 * NSTRIPSF), 0.0f), NSTRIPSF);
    float regp = 0.0f, ioup = 0.0f;
#pragma unroll
    for (int l = 0; l < NLANE; l++){
        if (mmask & (1 << l)){
            const float* la = s.laneA + l * 8;
            float d1 = yv - la[2] * NSTRIPSF;
            float d2 = pxc - la[3];
            float d3 = tv - la[4] * 180.0f;
            float tstart = rintf(la[2] * NSTRIPSF);
            float tlp = la[5] - (pstart - tstart);
            float d4 = lv - tlp;
            regp += smooth_l1(d1) + smooth_l1(d2) + smooth_l1(d3) + smooth_l1(d4);
            ioup += 1.0f - s.iouc[l * NP + tid];
        }
    }

    // ---- fused 4-way block sum over 192 threads ----
    float v0 = mfsum, v1 = focal, v2 = regp, v3 = ioup;
#pragma unroll
    for (int o2 = 16; o2; o2 >>= 1){
        v0 += __shfl_xor_sync(0xffffffffu, v0, o2);
        v1 += __shfl_xor_sync(0xffffffffu, v1, o2);
        v2 += __shfl_xor_sync(0xffffffffu, v2, o2);
        v3 += __shfl_xor_sync(0xffffffffu, v3, o2);
    }
    barL();
    if (lane == 0){ s.red[wid] = v0; s.red[8 + wid] = v1; s.red[16 + wid] = v2; s.red[24 + wid] = v3; }
    barL();
    if (tid == 0){
        float nmatch = 0.f, focal_s = 0.f, reg_s = 0.f, iou_s = 0.f;
#pragma unroll
        for (int w = 0; w < 6; w++){
            nmatch  += s.red[w];
            focal_s += s.red[8 + w];
            reg_s   += s.red[16 + w];
            iou_s   += s.red[24 + w];
        }
        float cls_term = has_t ? __fdividef(focal_s, num_t) : focal_s;
        float reg_term = has_t ? __fdividef(reg_s, fmaxf(nmatch * 4.0f, 1.0f)) : 0.0f;
        float iou_term = has_t ? __fdividef(iou_s, fmaxf(nmatch, 1.0f)) : 0.0f;
        g_partials[blk] = 2.0f * cls_term + 0.2f * reg_term + 2.0f * iou_term;

        __threadfence();
        unsigned prev = atomicAdd(&g_count, 1u);
        s.lastFlag = (prev == NBLK - 1) ? 1 : 0;
    }
    barL();

    // ---- last block: deterministic final reduction ----
    if (s.lastFlag){
        __threadfence();
        float acc = 0.0f;
#pragma unroll
        for (int k = 0; k < 8; k++)
            acc += g_partials[tid + k * 192];
#pragma unroll
        for (int o2 = 16; o2; o2 >>= 1)
            acc += __shfl_xor_sync(0xffffffffu, acc, o2);
        barL();
        if (lane == 0) s.red[wid] = acc;
        barL();
        if (tid == 0){
            float tot = 0.0f;
#pragma unroll
            for (int w = 0; w < 6; w++) tot += s.red[w];
            out[0] = tot / (float)NBLK + seg[0];
            g_count = 0;
        }
    }
}

extern "C" void kernel_launch(void* const* d_in, const int* in_sizes, int n_in,
                              void* d_out, int out_size)
{
    const float* pred = (const float*)d_in[0];
    const float* tgt  = (const float*)d_in[1];
    const float* seg  = (const float*)d_in[2];
    float* out = (float*)d_out;

    static int attr_set = 0;
    const int smem = (int)sizeof(SMLayout);
    if (!attr_set){
        cudaFuncSetAttribute(clr_main, cudaFuncAttributeMaxDynamicSharedMemorySize, smem);
        attr_set = 1;
    }
    clr_main<<<NBLK, NT, smem>>>(pred, tgt, seg, out);
}